// round 1
// baseline (speedup 1.0000x reference)
#include <cuda_runtime.h>
#include <math.h>
#include <stdint.h>

#define BB 2
#define NN 2048
#define DD 512
#define HH 8
#define DH 64
#define INNER 512
#define ROWS (BB*NN)            // 4096
#define BHN ((size_t)BB*HH*NN*DH)

// -------- scratch (device globals; no allocation allowed) --------
__device__ float g_xn[ROWS*DD];          // layernormed x, [b*n][d]
__device__ float g_lin[3*ROWS*INNER];    // q/k/v pointwise-conv outputs, [t][b*n][e]
__device__ float g_qkv[3*BB*HH*NN*DH];   // q/k/v after depthwise conv, [t][b][h][n][d]
__device__ float g_o[ROWS*INNER];        // attention output, [b*n][e]

// ---------------- LayerNorm: one block per row of 512 ----------------
__global__ void ln_kernel(const float* __restrict__ x,
                          const float* __restrict__ gamma,
                          const float* __restrict__ beta,
                          float* __restrict__ xn) {
    int row = blockIdx.x;
    const float* xr = x + (size_t)row * DD;
    float* outr = xn + (size_t)row * DD;
    int t = threadIdx.x;                       // 256 threads, 2 elems each
    float v0 = xr[t], v1 = xr[t + 256];
    float s = v0 + v1;
    float sq = v0 * v0 + v1 * v1;
    #pragma unroll
    for (int o = 16; o > 0; o >>= 1) {
        s  += __shfl_xor_sync(0xffffffffu, s, o);
        sq += __shfl_xor_sync(0xffffffffu, sq, o);
    }
    __shared__ float ss[8], ssq[8];
    if ((t & 31) == 0) { ss[t >> 5] = s; ssq[t >> 5] = sq; }
    __syncthreads();
    s = 0.f; sq = 0.f;
    #pragma unroll
    for (int i = 0; i < 8; ++i) { s += ss[i]; sq += ssq[i]; }
    float mean = s * (1.f / DD);
    float var  = sq * (1.f / DD) - mean * mean;
    float rstd = rsqrtf(var + 1e-5f);
    outr[t]       = (v0 - mean) * rstd * gamma[t]       + beta[t];
    outr[t + 256] = (v1 - mean) * rstd * gamma[t + 256] + beta[t + 256];
}

// ---------------- SGEMM: C[m][e] = sum_k A[m][k] * W[e][k] ----------------
// 64x64 block tile, 256 threads (16x16), 4x4 microtile, K-chunk 16.
// gridDim.z selects among up to 3 (W, C) pairs (fused q/k/v projections).
__global__ void sgemm_nt(const float* __restrict__ A,
                         const float* __restrict__ W0,
                         const float* __restrict__ W1,
                         const float* __restrict__ W2,
                         float* __restrict__ C0,
                         float* __restrict__ C1,
                         float* __restrict__ C2,
                         int M, int NO, int K) {
    const float* W = (blockIdx.z == 0) ? W0 : (blockIdx.z == 1) ? W1 : W2;
    float*       C = (blockIdx.z == 0) ? C0 : (blockIdx.z == 1) ? C1 : C2;

    __shared__ float As[16][64];
    __shared__ float Ws[16][64];
    int m0 = blockIdx.y * 64, e0 = blockIdx.x * 64;
    int tid = threadIdx.x;
    int tx = tid & 15, ty = tid >> 4;
    int lr = tid >> 2;              // 0..63 (row within tile for loads)
    int lk = (tid & 3) << 2;        // 0,4,8,12 (k offset for float4 loads)
    float acc[4][4] = {};
    const float* Arow = A + (size_t)(m0 + lr) * K + lk;
    const float* Wrow = W + (size_t)(e0 + lr) * K + lk;
    for (int k0 = 0; k0 < K; k0 += 16) {
        float4 a = *(const float4*)(Arow + k0);
        float4 w = *(const float4*)(Wrow + k0);
        As[lk + 0][lr] = a.x; As[lk + 1][lr] = a.y; As[lk + 2][lr] = a.z; As[lk + 3][lr] = a.w;
        Ws[lk + 0][lr] = w.x; Ws[lk + 1][lr] = w.y; Ws[lk + 2][lr] = w.z; Ws[lk + 3][lr] = w.w;
        __syncthreads();
        #pragma unroll
        for (int kk = 0; kk < 16; ++kk) {
            float av[4], wv[4];
            #pragma unroll
            for (int i = 0; i < 4; ++i) av[i] = As[kk][ty * 4 + i];
            #pragma unroll
            for (int j = 0; j < 4; ++j) wv[j] = Ws[kk][tx * 4 + j];
            #pragma unroll
            for (int i = 0; i < 4; ++i)
                #pragma unroll
                for (int j = 0; j < 4; ++j)
                    acc[i][j] += av[i] * wv[j];
        }
        __syncthreads();
    }
    #pragma unroll
    for (int i = 0; i < 4; ++i) {
        float4 r = make_float4(acc[i][0], acc[i][1], acc[i][2], acc[i][3]);
        *(float4*)(C + (size_t)(m0 + ty * 4 + i) * NO + e0 + tx * 4) = r;
    }
}

// ------- depthwise causal conv (k=3) + head split + q scale -------
__global__ void conv_split_kernel(const float* __restrict__ lin,
                                  const float* __restrict__ wqd,
                                  const float* __restrict__ wkd,
                                  const float* __restrict__ wvd,
                                  float* __restrict__ qkv) {
    int idx = blockIdx.x * 256 + threadIdx.x;      // over ROWS*INNER = 2^21
    int e = idx & (INNER - 1);
    int n = (idx >> 9) & (NN - 1);
    int b = idx >> 20;
    int h = e >> 6, d = e & 63;
    size_t dst = (((size_t)(b * HH + h) * NN + n) * DH + d);
    #pragma unroll
    for (int t = 0; t < 3; ++t) {
        const float* L = lin + (size_t)t * ROWS * INNER;
        const float* wd = (t == 0) ? wqd : (t == 1) ? wkd : wvd;
        float y2 = L[idx];
        float y1 = (n >= 1) ? L[idx - INNER] : 0.f;
        float y0 = (n >= 2) ? L[idx - 2 * INNER] : 0.f;
        float v = wd[e * 3 + 0] * y0 + wd[e * 3 + 1] * y1 + wd[e * 3 + 2] * y2;
        if (t == 0) v *= 0.125f;                   // DIM_HEAD^-0.5
        qkv[(size_t)t * BHN + dst] = v;
    }
}

// ---------------- Flash attention, fp32, causal + ALiBi ----------------
// Br=Bc=64, 256 threads (16x16), 4x4 microtiles, online softmax in registers
// via 16-lane shfl reductions.
#define SMEM_ATTN (4 * 64 * 65 * 4)

__global__ void attn_kernel(const float* __restrict__ qkv, float* __restrict__ o) {
    extern __shared__ float sm[];
    float* Qs = sm;                  // [64][65]
    float* Ks = Qs + 64 * 65;        // [64][65]
    float* Vs = Ks + 64 * 65;        // [64][65]
    float* Ps = Vs + 64 * 65;        // [64][65]

    int qt = blockIdx.x, bh = blockIdx.y;
    int b = bh >> 3, h = bh & 7;
    int qs = qt * 64;
    const float* qb = qkv + (size_t)bh * NN * DH;
    const float* kb = qkv + BHN + (size_t)bh * NN * DH;
    const float* vb = qkv + 2 * BHN + (size_t)bh * NN * DH;

    int tid = threadIdx.x;
    int tx = tid & 15, ty = tid >> 4;

    for (int i = tid; i < 64 * 64; i += 256) {
        int rr = i >> 6, cc = i & 63;
        Qs[rr * 65 + cc] = qb[(size_t)(qs + rr) * DH + cc];
    }

    float m[4], l[4], acc[4][4];
    #pragma unroll
    for (int i = 0; i < 4; ++i) {
        m[i] = -1e30f; l[i] = 0.f;
        #pragma unroll
        for (int j = 0; j < 4; ++j) acc[i][j] = 0.f;
    }
    float slope = exp2f(-(float)(h + 1));
    int ig[4];
    #pragma unroll
    for (int i = 0; i < 4; ++i) ig[i] = qs + ty * 4 + i;

    __syncthreads();
    int ntile = qt + 1;                      // causal: only tiles up to diagonal
    for (int t = 0; t < ntile; ++t) {
        int ks0 = t * 64;
        for (int i = tid; i < 64 * 64; i += 256) {
            int rr = i >> 6, cc = i & 63;
            Ks[rr * 65 + cc] = kb[(size_t)(ks0 + rr) * DH + cc];
            Vs[rr * 65 + cc] = vb[(size_t)(ks0 + rr) * DH + cc];
        }
        __syncthreads();

        // S = Q K^T (4x4 microtile per thread)
        float s[4][4] = {};
        #pragma unroll 16
        for (int kk = 0; kk < 64; ++kk) {
            float av[4], bv[4];
            #pragma unroll
            for (int i = 0; i < 4; ++i) av[i] = Qs[(ty * 4 + i) * 65 + kk];
            #pragma unroll
            for (int j = 0; j < 4; ++j) bv[j] = Ks[(tx * 4 + j) * 65 + kk];
            #pragma unroll
            for (int i = 0; i < 4; ++i)
                #pragma unroll
                for (int j = 0; j < 4; ++j)
                    s[i][j] += av[i] * bv[j];
        }
        // ALiBi bias + causal mask
        #pragma unroll
        for (int i = 0; i < 4; ++i)
            #pragma unroll
            for (int j = 0; j < 4; ++j) {
                int jg = ks0 + tx * 4 + j;
                s[i][j] = (jg <= ig[i]) ? s[i][j] - slope * (float)(ig[i] - jg)
                                        : -1e30f;
            }
        // online softmax: per-row reduce across the 16 tx lanes (same warp half)
        #pragma unroll
        for (int i = 0; i < 4; ++i) {
            float rm = fmaxf(fmaxf(s[i][0], s[i][1]), fmaxf(s[i][2], s[i][3]));
            #pragma unroll
            for (int off = 8; off > 0; off >>= 1)
                rm = fmaxf(rm, __shfl_xor_sync(0xffffffffu, rm, off));
            float mn = fmaxf(m[i], rm);
            float al = __expf(m[i] - mn);
            float ls = 0.f;
            #pragma unroll
            for (int j = 0; j < 4; ++j) {
                s[i][j] = __expf(s[i][j] - mn);
                ls += s[i][j];
            }
            #pragma unroll
            for (int off = 8; off > 0; off >>= 1)
                ls += __shfl_xor_sync(0xffffffffu, ls, off);
            l[i] = l[i] * al + ls;
            m[i] = mn;
            #pragma unroll
            for (int j = 0; j < 4; ++j) acc[i][j] *= al;
        }
        // stash P for the PV outer product
        #pragma unroll
        for (int i = 0; i < 4; ++i)
            #pragma unroll
            for (int j = 0; j < 4; ++j)
                Ps[(ty * 4 + i) * 65 + tx * 4 + j] = s[i][j];
        __syncthreads();
        // O += P @ V
        #pragma unroll 16
        for (int j64 = 0; j64 < 64; ++j64) {
            float pv[4], vv[4];
            #pragma unroll
            for (int i = 0; i < 4; ++i) pv[i] = Ps[(ty * 4 + i) * 65 + j64];
            #pragma unroll
            for (int j = 0; j < 4; ++j) vv[j] = Vs[j64 * 65 + tx * 4 + j];
            #pragma unroll
            for (int i = 0; i < 4; ++i)
                #pragma unroll
                for (int j = 0; j < 4; ++j)
                    acc[i][j] += pv[i] * vv[j];
        }
        __syncthreads();
    }

    // normalize and write out in [b][n][h*64+d] layout for the output GEMM
    #pragma unroll
    for (int i = 0; i < 4; ++i) {
        float inv = 1.f / l[i];
        int n = qs + ty * 4 + i;
        size_t base = ((size_t)b * NN + n) * INNER + h * DH + tx * 4;
        #pragma unroll
        for (int j = 0; j < 4; ++j)
            o[base + j] = acc[i][j] * inv;
    }
}

extern "C" void kernel_launch(void* const* d_in, const int* in_sizes, int n_in,
                              void* d_out, int out_size) {
    const float* x     = (const float*)d_in[0];
    const float* gamma = (const float*)d_in[1];
    const float* beta  = (const float*)d_in[2];
    const float* wq1   = (const float*)d_in[3];
    const float* wqd   = (const float*)d_in[4];
    const float* wk1   = (const float*)d_in[5];
    const float* wkd   = (const float*)d_in[6];
    const float* wv1   = (const float*)d_in[7];
    const float* wvd   = (const float*)d_in[8];
    const float* wout  = (const float*)d_in[9];
    float* out = (float*)d_out;

    float *xn, *lin, *qkv, *o;
    cudaGetSymbolAddress((void**)&xn,  g_xn);
    cudaGetSymbolAddress((void**)&lin, g_lin);
    cudaGetSymbolAddress((void**)&qkv, g_qkv);
    cudaGetSymbolAddress((void**)&o,   g_o);

    // 1) LayerNorm
    ln_kernel<<<ROWS, 256>>>(x, gamma, beta, xn);

    // 2) three pointwise projections in one launch (gridDim.z = 3)
    dim3 g1(INNER / 64, ROWS / 64, 3);
    sgemm_nt<<<g1, 256>>>(xn, wq1, wk1, wv1,
                          lin, lin + (size_t)ROWS * INNER, lin + 2 * (size_t)ROWS * INNER,
                          ROWS, INNER, DD);

    // 3) depthwise causal conv + head split + q scale
    conv_split_kernel<<<(ROWS * INNER) / 256, 256>>>(lin, wqd, wkd, wvd, qkv);

    // 4) flash attention with ALiBi + causal mask
    cudaFuncSetAttribute(attn_kernel, cudaFuncAttributeMaxDynamicSharedMemorySize, SMEM_ATTN);
    attn_kernel<<<dim3(NN / 64, BB * HH), 256, SMEM_ATTN>>>(qkv, o);

    // 5) output projection straight into d_out
    dim3 g2(DD / 64, ROWS / 64, 1);
    sgemm_nt<<<g2, 256>>>(o, wout, wout, wout, out, out, out, ROWS, DD, INNER);
}

// round 4
// speedup vs baseline: 1.8318x; 1.8318x over previous
#include <cuda_runtime.h>
#include <math.h>
#include <stdint.h>

#define BB 2
#define NN 2048
#define DD 512
#define HH 8
#define DH 64
#define INNER 512
#define ROWS (BB*NN)            // 4096
#define BHN ((size_t)BB*HH*NN*DH)

// -------- scratch (device globals; no allocation allowed) --------
__device__ float g_xn[ROWS*DD];
__device__ float g_lin[3*ROWS*INNER];
__device__ float g_qkv[3*BB*HH*NN*DH];
__device__ float g_o[ROWS*INNER];

// ---------------- helpers ----------------
__device__ __forceinline__ uint32_t smem_u32(const void* p) {
    uint32_t a;
    asm("{ .reg .u64 t; cvta.to.shared.u64 t, %1; cvt.u32.u64 %0, t; }" : "=r"(a) : "l"(p));
    return a;
}
__device__ __forceinline__ void mma_tf32(float* c, const uint32_t* a, const uint32_t* b) {
    asm volatile(
        "mma.sync.aligned.m16n8k8.row.col.f32.tf32.tf32.f32 "
        "{%0,%1,%2,%3}, {%4,%5,%6,%7}, {%8,%9}, {%0,%1,%2,%3};"
        : "+f"(c[0]), "+f"(c[1]), "+f"(c[2]), "+f"(c[3])
        : "r"(a[0]), "r"(a[1]), "r"(a[2]), "r"(a[3]), "r"(b[0]), "r"(b[1]));
}
// fp32 -> round-to-nearest tf32 (bits in fp32 container)
__device__ __forceinline__ uint32_t f2tf(float x) {
    uint32_t r;
    asm("cvt.rna.tf32.f32 %0, %1;" : "=r"(r) : "f"(x));
    return r;
}
// split x into tf32 big + tf32-able residual
__device__ __forceinline__ void tfsplit(float x, uint32_t& big, uint32_t& small) {
    big = f2tf(x);
    small = __float_as_uint(x - __uint_as_float(big));
}
#define CP_ASYNC16(dst, src) \
    asm volatile("cp.async.cg.shared.global [%0], [%1], 16;" :: "r"(dst), "l"(src) : "memory")
#define CP_COMMIT() asm volatile("cp.async.commit_group;" ::: "memory")
#define CP_WAIT(n)  asm volatile("cp.async.wait_group %0;" :: "n"(n) : "memory")

// ---------------- LayerNorm ----------------
__global__ void ln_kernel(const float* __restrict__ x,
                          const float* __restrict__ gamma,
                          const float* __restrict__ beta,
                          float* __restrict__ xn) {
    int row = blockIdx.x;
    const float* xr = x + (size_t)row * DD;
    float* outr = xn + (size_t)row * DD;
    int t = threadIdx.x;
    float v0 = xr[t], v1 = xr[t + 256];
    float s = v0 + v1;
    float sq = v0 * v0 + v1 * v1;
    #pragma unroll
    for (int o = 16; o > 0; o >>= 1) {
        s  += __shfl_xor_sync(0xffffffffu, s, o);
        sq += __shfl_xor_sync(0xffffffffu, sq, o);
    }
    __shared__ float ss[8], ssq[8];
    if ((t & 31) == 0) { ss[t >> 5] = s; ssq[t >> 5] = sq; }
    __syncthreads();
    s = 0.f; sq = 0.f;
    #pragma unroll
    for (int i = 0; i < 8; ++i) { s += ss[i]; sq += ssq[i]; }
    float mean = s * (1.f / DD);
    float var  = sq * (1.f / DD) - mean * mean;
    float rstd = rsqrtf(var + 1e-5f);
    outr[t]       = (v0 - mean) * rstd * gamma[t]       + beta[t];
    outr[t + 256] = (v1 - mean) * rstd * gamma[t + 256] + beta[t + 256];
}

// ---------------- 3xTF32 mma.sync GEMM ----------------
// C[m][e] = sum_k A[m][k] * W[e][k]; 128x128 tile, 8 warps (64x32 each),
// K-chunk 32, cp.async double buffer. 3xTF32: bb + sb + bs passes.
#define GP 36
#define GCHUNK (128 * GP)
#define SM_GEMM (4 * GCHUNK * 4)

__global__ void __launch_bounds__(256)
gemm_mma(const float* __restrict__ A,
         const float* __restrict__ W0, const float* __restrict__ W1, const float* __restrict__ W2,
         float* __restrict__ C0, float* __restrict__ C1, float* __restrict__ C2,
         int NO, int K) {
    const float* W = (blockIdx.z == 0) ? W0 : (blockIdx.z == 1) ? W1 : W2;
    float*       C = (blockIdx.z == 0) ? C0 : (blockIdx.z == 1) ? C1 : C2;

    extern __shared__ float sm[];
    float* sA = sm;
    float* sW = sm + 2 * GCHUNK;

    int tid = threadIdx.x;
    int wid = tid >> 5, lane = tid & 31;
    int wm = wid >> 2, wn = wid & 3;
    int lq = lane >> 2, lm = lane & 3;
    int m0 = blockIdx.y * 128, e0 = blockIdx.x * 128;

    int lrow = tid >> 1;
    int lc4  = (tid & 1) << 2;
    const int nchunk = K >> 5;

    float acc[4][4][4];
    #pragma unroll
    for (int i = 0; i < 4; ++i)
        #pragma unroll
        for (int j = 0; j < 4; ++j)
            #pragma unroll
            for (int q = 0; q < 4; ++q) acc[i][j][q] = 0.f;

    uint32_t sAu = smem_u32(sA), sWu = smem_u32(sW);

    auto load_chunk = [&](int c, int buf) {
        int k0 = c << 5;
        const float* Ag = A + (size_t)(m0 + lrow) * K + k0 + lc4 * 4;
        const float* Wg = W + (size_t)(e0 + lrow) * K + k0 + lc4 * 4;
        uint32_t dstA = sAu + (uint32_t)(buf * GCHUNK + lrow * GP + lc4 * 4) * 4;
        uint32_t dstW = sWu + (uint32_t)(buf * GCHUNK + lrow * GP + lc4 * 4) * 4;
        #pragma unroll
        for (int i = 0; i < 4; ++i) {
            CP_ASYNC16(dstA + i * 16, Ag + i * 4);
            CP_ASYNC16(dstW + i * 16, Wg + i * 4);
        }
    };

    load_chunk(0, 0);
    CP_COMMIT();

    for (int c = 0; c < nchunk; ++c) {
        if (c + 1 < nchunk) {
            load_chunk(c + 1, (c + 1) & 1);
            CP_COMMIT();
            CP_WAIT(1);
        } else {
            CP_WAIT(0);
        }
        __syncthreads();
        const float* sAb = sA + (c & 1) * GCHUNK;
        const float* sWb = sW + (c & 1) * GCHUNK;
        #pragma unroll
        for (int k4 = 0; k4 < 4; ++k4) {
            int kc = k4 * 8;
            uint32_t ab[4][4], as_[4][4], bb[4][2], bs[4][2];
            #pragma unroll
            for (int mt = 0; mt < 4; ++mt) {
                int r = wm * 64 + mt * 16 + lq;
                tfsplit(sAb[r * GP + kc + lm],           ab[mt][0], as_[mt][0]);
                tfsplit(sAb[(r + 8) * GP + kc + lm],     ab[mt][1], as_[mt][1]);
                tfsplit(sAb[r * GP + kc + lm + 4],       ab[mt][2], as_[mt][2]);
                tfsplit(sAb[(r + 8) * GP + kc + lm + 4], ab[mt][3], as_[mt][3]);
            }
            #pragma unroll
            for (int nt = 0; nt < 4; ++nt) {
                int n = wn * 32 + nt * 8 + lq;
                tfsplit(sWb[n * GP + kc + lm],     bb[nt][0], bs[nt][0]);
                tfsplit(sWb[n * GP + kc + lm + 4], bb[nt][1], bs[nt][1]);
            }
            #pragma unroll
            for (int mt = 0; mt < 4; ++mt)
                #pragma unroll
                for (int nt = 0; nt < 4; ++nt) {
                    mma_tf32(acc[mt][nt], ab[mt],  bb[nt]);
                    mma_tf32(acc[mt][nt], as_[mt], bb[nt]);
                    mma_tf32(acc[mt][nt], ab[mt],  bs[nt]);
                }
        }
        __syncthreads();
    }

    #pragma unroll
    for (int mt = 0; mt < 4; ++mt) {
        int r0 = m0 + wm * 64 + mt * 16 + lq;
        #pragma unroll
        for (int nt = 0; nt < 4; ++nt) {
            int c0 = e0 + wn * 32 + nt * 8 + lm * 2;
            *(float2*)(C + (size_t)r0 * NO + c0)       = make_float2(acc[mt][nt][0], acc[mt][nt][1]);
            *(float2*)(C + (size_t)(r0 + 8) * NO + c0) = make_float2(acc[mt][nt][2], acc[mt][nt][3]);
        }
    }
}

// ------- depthwise causal conv (k=3) + head split + q scale -------
__global__ void conv_split_kernel(const float* __restrict__ lin,
                                  const float* __restrict__ wqd,
                                  const float* __restrict__ wkd,
                                  const float* __restrict__ wvd,
                                  float* __restrict__ qkv) {
    int idx = blockIdx.x * 256 + threadIdx.x;
    int e = idx & (INNER - 1);
    int n = (idx >> 9) & (NN - 1);
    int b = idx >> 20;
    int h = e >> 6, d = e & 63;
    size_t dst = (((size_t)(b * HH + h) * NN + n) * DH + d);
    #pragma unroll
    for (int t = 0; t < 3; ++t) {
        const float* L = lin + (size_t)t * ROWS * INNER;
        const float* wd = (t == 0) ? wqd : (t == 1) ? wkd : wvd;
        float y2 = L[idx];
        float y1 = (n >= 1) ? L[idx - INNER] : 0.f;
        float y0 = (n >= 2) ? L[idx - 2 * INNER] : 0.f;
        float v = wd[e * 3 + 0] * y0 + wd[e * 3 + 1] * y1 + wd[e * 3 + 2] * y2;
        if (t == 0) v *= 0.125f;
        qkv[(size_t)t * BHN + dst] = v;
    }
}

// ---------------- Flash attention via 3xTF32 mma.sync ----------------
#define AP 68
#define SMEM_ATTN (4 * 64 * AP * 4)

__global__ void __launch_bounds__(128)
attn_kernel(const float* __restrict__ qkv, float* __restrict__ o) {
    extern __shared__ float smf[];
    float* Qs = smf;
    float* Ks = Qs + 64 * AP;
    float* Vs = Ks + 64 * AP;
    float* Ps = Vs + 64 * AP;

    int qt = gridDim.x - 1 - blockIdx.x;
    int bh = blockIdx.y;
    int b = bh >> 3, h = bh & 7;
    int qs = qt * 64;
    const float* qb = qkv + (size_t)bh * NN * DH;
    const float* kb = qkv + BHN + (size_t)bh * NN * DH;
    const float* vb = qkv + 2 * BHN + (size_t)bh * NN * DH;

    int tid = threadIdx.x;
    int wid = tid >> 5, lane = tid & 31;
    int lq = lane >> 2, lm = lane & 3;
    int wr = wid * 16;

    #pragma unroll
    for (int i = 0; i < 8; ++i) {
        int idx = i * 128 + tid;
        int rr = idx >> 4, c4 = idx & 15;
        *(float4*)(Qs + rr * AP + c4 * 4) = *(const float4*)(qb + (size_t)(qs + rr) * DH + c4 * 4);
    }

    float acc_o[8][4];
    #pragma unroll
    for (int nt = 0; nt < 8; ++nt)
        #pragma unroll
        for (int q = 0; q < 4; ++q) acc_o[nt][q] = 0.f;
    float m0r = -1e30f, m1r = -1e30f, l0r = 0.f, l1r = 0.f;
    float slope = exp2f(-(float)(h + 1));
    int ig0 = qs + wr + lq, ig1 = ig0 + 8;

    __syncthreads();
    int ntile = qt + 1;
    for (int t = 0; t < ntile; ++t) {
        int ks0 = t * 64;
        #pragma unroll
        for (int i = 0; i < 8; ++i) {
            int idx = i * 128 + tid;
            int rr = idx >> 4, c4 = idx & 15;
            *(float4*)(Ks + rr * AP + c4 * 4) = *(const float4*)(kb + (size_t)(ks0 + rr) * DH + c4 * 4);
            *(float4*)(Vs + rr * AP + c4 * 4) = *(const float4*)(vb + (size_t)(ks0 + rr) * DH + c4 * 4);
        }
        __syncthreads();

        // S = Q K^T, 3xTF32
        float acc_s[8][4];
        #pragma unroll
        for (int nt = 0; nt < 8; ++nt)
            #pragma unroll
            for (int q = 0; q < 4; ++q) acc_s[nt][q] = 0.f;
        #pragma unroll
        for (int ks = 0; ks < 8; ++ks) {
            int kc = ks * 8;
            uint32_t ab[4], as_[4];
            tfsplit(Qs[(wr + lq) * AP + kc + lm],           ab[0], as_[0]);
            tfsplit(Qs[(wr + lq + 8) * AP + kc + lm],       ab[1], as_[1]);
            tfsplit(Qs[(wr + lq) * AP + kc + lm + 4],       ab[2], as_[2]);
            tfsplit(Qs[(wr + lq + 8) * AP + kc + lm + 4],   ab[3], as_[3]);
            #pragma unroll
            for (int nt = 0; nt < 8; ++nt) {
                uint32_t bb[2], bs[2];
                tfsplit(Ks[(nt * 8 + lq) * AP + kc + lm],     bb[0], bs[0]);
                tfsplit(Ks[(nt * 8 + lq) * AP + kc + lm + 4], bb[1], bs[1]);
                mma_tf32(acc_s[nt], ab,  bb);
                mma_tf32(acc_s[nt], as_, bb);
                mma_tf32(acc_s[nt], ab,  bs);
            }
        }

        // bias + causal mask
        #pragma unroll
        for (int nt = 0; nt < 8; ++nt) {
            int jg = ks0 + nt * 8 + lm * 2;
            acc_s[nt][0] = (jg     <= ig0) ? acc_s[nt][0] - slope * (float)(ig0 - jg)     : -1e30f;
            acc_s[nt][1] = (jg + 1 <= ig0) ? acc_s[nt][1] - slope * (float)(ig0 - jg - 1) : -1e30f;
            acc_s[nt][2] = (jg     <= ig1) ? acc_s[nt][2] - slope * (float)(ig1 - jg)     : -1e30f;
            acc_s[nt][3] = (jg + 1 <= ig1) ? acc_s[nt][3] - slope * (float)(ig1 - jg - 1) : -1e30f;
        }

        // online softmax
        float rm0 = -1e30f, rm1 = -1e30f;
        #pragma unroll
        for (int nt = 0; nt < 8; ++nt) {
            rm0 = fmaxf(rm0, fmaxf(acc_s[nt][0], acc_s[nt][1]));
            rm1 = fmaxf(rm1, fmaxf(acc_s[nt][2], acc_s[nt][3]));
        }
        rm0 = fmaxf(rm0, __shfl_xor_sync(0xffffffffu, rm0, 1));
        rm0 = fmaxf(rm0, __shfl_xor_sync(0xffffffffu, rm0, 2));
        rm1 = fmaxf(rm1, __shfl_xor_sync(0xffffffffu, rm1, 1));
        rm1 = fmaxf(rm1, __shfl_xor_sync(0xffffffffu, rm1, 2));
        float mn0 = fmaxf(m0r, rm0), mn1 = fmaxf(m1r, rm1);
        float al0 = __expf(m0r - mn0), al1 = __expf(m1r - mn1);
        float ls0 = 0.f, ls1 = 0.f;
        #pragma unroll
        for (int nt = 0; nt < 8; ++nt) {
            acc_s[nt][0] = __expf(acc_s[nt][0] - mn0);
            acc_s[nt][1] = __expf(acc_s[nt][1] - mn0);
            acc_s[nt][2] = __expf(acc_s[nt][2] - mn1);
            acc_s[nt][3] = __expf(acc_s[nt][3] - mn1);
            ls0 += acc_s[nt][0] + acc_s[nt][1];
            ls1 += acc_s[nt][2] + acc_s[nt][3];
        }
        ls0 += __shfl_xor_sync(0xffffffffu, ls0, 1);
        ls0 += __shfl_xor_sync(0xffffffffu, ls0, 2);
        ls1 += __shfl_xor_sync(0xffffffffu, ls1, 1);
        ls1 += __shfl_xor_sync(0xffffffffu, ls1, 2);
        l0r = l0r * al0 + ls0;  m0r = mn0;
        l1r = l1r * al1 + ls1;  m1r = mn1;
        #pragma unroll
        for (int nt = 0; nt < 8; ++nt) {
            acc_o[nt][0] *= al0; acc_o[nt][1] *= al0;
            acc_o[nt][2] *= al1; acc_o[nt][3] *= al1;
        }

        #pragma unroll
        for (int nt = 0; nt < 8; ++nt) {
            int cc = nt * 8 + lm * 2;
            *(float2*)(Ps + (wr + lq) * AP + cc)     = make_float2(acc_s[nt][0], acc_s[nt][1]);
            *(float2*)(Ps + (wr + lq + 8) * AP + cc) = make_float2(acc_s[nt][2], acc_s[nt][3]);
        }
        __syncwarp();

        // O += P @ V, 3xTF32
        #pragma unroll
        for (int ks = 0; ks < 8; ++ks) {
            int kc = ks * 8;
            uint32_t ab[4], as_[4];
            tfsplit(Ps[(wr + lq) * AP + kc + lm],         ab[0], as_[0]);
            tfsplit(Ps[(wr + lq + 8) * AP + kc + lm],     ab[1], as_[1]);
            tfsplit(Ps[(wr + lq) * AP + kc + lm + 4],     ab[2], as_[2]);
            tfsplit(Ps[(wr + lq + 8) * AP + kc + lm + 4], ab[3], as_[3]);
            #pragma unroll
            for (int nt = 0; nt < 8; ++nt) {
                uint32_t bb[2], bs[2];
                tfsplit(Vs[(kc + lm) * AP + nt * 8 + lq],     bb[0], bs[0]);
                tfsplit(Vs[(kc + lm + 4) * AP + nt * 8 + lq], bb[1], bs[1]);
                mma_tf32(acc_o[nt], ab,  bb);
                mma_tf32(acc_o[nt], as_, bb);
                mma_tf32(acc_o[nt], ab,  bs);
            }
        }
        __syncthreads();
    }

    float inv0 = 1.f / l0r, inv1 = 1.f / l1r;
    int n0 = qs + wr + lq, n1 = n0 + 8;
    #pragma unroll
    for (int nt = 0; nt < 8; ++nt) {
        int cc = h * DH + nt * 8 + lm * 2;
        *(float2*)(o + ((size_t)b * NN + n0) * INNER + cc) =
            make_float2(acc_o[nt][0] * inv0, acc_o[nt][1] * inv0);
        *(float2*)(o + ((size_t)b * NN + n1) * INNER + cc) =
            make_float2(acc_o[nt][2] * inv1, acc_o[nt][3] * inv1);
    }
}

extern "C" void kernel_launch(void* const* d_in, const int* in_sizes, int n_in,
                              void* d_out, int out_size) {
    const float* x     = (const float*)d_in[0];
    const float* gamma = (const float*)d_in[1];
    const float* beta  = (const float*)d_in[2];
    const float* wq1   = (const float*)d_in[3];
    const float* wqd   = (const float*)d_in[4];
    const float* wk1   = (const float*)d_in[5];
    const float* wkd   = (const float*)d_in[6];
    const float* wv1   = (const float*)d_in[7];
    const float* wvd   = (const float*)d_in[8];
    const float* wout  = (const float*)d_in[9];
    float* out = (float*)d_out;

    float *xn, *lin, *qkv, *o;
    cudaGetSymbolAddress((void**)&xn,  g_xn);
    cudaGetSymbolAddress((void**)&lin, g_lin);
    cudaGetSymbolAddress((void**)&qkv, g_qkv);
    cudaGetSymbolAddress((void**)&o,   g_o);

    cudaFuncSetAttribute(gemm_mma, cudaFuncAttributeMaxDynamicSharedMemorySize, SM_GEMM);
    cudaFuncSetAttribute(attn_kernel, cudaFuncAttributeMaxDynamicSharedMemorySize, SMEM_ATTN);

    ln_kernel<<<ROWS, 256>>>(x, gamma, beta, xn);

    dim3 g1(INNER / 128, ROWS / 128, 3);
    gemm_mma<<<g1, 256, SM_GEMM>>>(xn, wq1, wk1, wv1,
                                   lin, lin + (size_t)ROWS * INNER, lin + 2 * (size_t)ROWS * INNER,
                                   INNER, DD);

    conv_split_kernel<<<(ROWS * INNER) / 256, 256>>>(lin, wqd, wkd, wvd, qkv);

    attn_kernel<<<dim3(NN / 64, BB * HH), 128, SMEM_ATTN>>>(qkv, o);

    dim3 g2(DD / 128, ROWS / 128, 1);
    gemm_mma<<<g2, 256, SM_GEMM>>>(o, wout, wout, wout, out, out, out, DD, INNER);
}